// round 6
// baseline (speedup 1.0000x reference)
#include <cuda_runtime.h>

// ---------------- scratch (no allocations allowed) ----------------
__device__ float g_y1a[2*32*4096];     // after pointwise squeeze (b,32,64,64)
__device__ float g_y5[2*64*1024];      // after channel attn + nidx perm
__device__ float g_os[2*64*2*1024];    // spatial attn output per head (b,h,d,n)

// ---------------- K1: pointwise squeeze 64->32 over (2,64,64,64) ----------------
__global__ void k_squeeze1(const float* __restrict__ x, const float* __restrict__ w,
                           const float* __restrict__ bias){
  __shared__ float ws[512];
  int t = threadIdx.x;
  int og = blockIdx.y, b = blockIdx.z;
  for (int i=t;i<512;i+=256) ws[i] = w[og*512 + i];
  __syncthreads();
  int pos = blockIdx.x*256 + t;
  float acc[8];
  #pragma unroll
  for (int oo=0;oo<8;oo++) acc[oo] = bias[og*8+oo];
  const float* xp = x + b*262144 + pos;
  #pragma unroll 4
  for (int c=0;c<64;c++){
    float xv = xp[c<<12];
    #pragma unroll
    for (int oo=0;oo<8;oo++) acc[oo] = fmaf(xv, ws[oo*64+c], acc[oo]);
  }
  #pragma unroll
  for (int oo=0;oo<8;oo++) g_y1a[((b*32+og*8+oo)<<12)+pos] = acc[oo];
}

// ---------------- K2: depthwise 2x2 s2 (fused) + channel attention via moments ----------------
__global__ void k_chattn(const float* __restrict__ w2, const float* __restrict__ b2,
                         const float* __restrict__ wqkv, const float* __restrict__ bqkv,
                         const float* __restrict__ tvec, const float* __restrict__ wf,
                         const float* __restrict__ bf){
  int h2 = blockIdx.x, b = blockIdx.y;       // h2 in [0,32)
  __shared__ float ch0[1024], ch1[1024];
  __shared__ float red[8][5];
  __shared__ float coef[6];
  int t = threadIdx.x;
  int oc0 = h2, oc1 = h2 + 32;
  int g0 = oc0>>1, g1 = oc1>>1;
  const float* s0b = g_y1a + ((b*32+g0)<<12);
  const float* s1b = g_y1a + ((b*32+g1)<<12);
  float w00=w2[oc0*4],w01=w2[oc0*4+1],w02=w2[oc0*4+2],w03=w2[oc0*4+3],bb0=b2[oc0];
  float w10=w2[oc1*4],w11=w2[oc1*4+1],w12=w2[oc1*4+2],w13=w2[oc1*4+3],bb1=b2[oc1];
  float s0=0.f,s1=0.f,m00=0.f,m01=0.f,m11=0.f;
  for (int i=t;i<1024;i+=256){
    int hh=i>>5, ww=i&31;
    int off = (hh<<7) + (ww<<1);
    const float* p0 = s0b + off;
    const float* p1 = s1b + off;
    float a = bb0 + p0[0]*w00 + p0[1]*w01 + p0[64]*w02 + p0[65]*w03;
    float c = bb1 + p1[0]*w10 + p1[1]*w11 + p1[64]*w12 + p1[65]*w13;
    ch0[i]=a; ch1[i]=c;
    s0+=a; s1+=c; m00=fmaf(a,a,m00); m01=fmaf(a,c,m01); m11=fmaf(c,c,m11);
  }
  #pragma unroll
  for (int off=16;off;off>>=1){
    s0 += __shfl_down_sync(0xffffffffu,s0,off);
    s1 += __shfl_down_sync(0xffffffffu,s1,off);
    m00+= __shfl_down_sync(0xffffffffu,m00,off);
    m01+= __shfl_down_sync(0xffffffffu,m01,off);
    m11+= __shfl_down_sync(0xffffffffu,m11,off);
  }
  if ((t&31)==0){ int w=t>>5; red[w][0]=s0; red[w][1]=s1; red[w][2]=m00; red[w][3]=m01; red[w][4]=m11; }
  __syncthreads();
  if (t==0){
    float S1v[2]={0.f,0.f}, S200=0.f,S201=0.f,S211=0.f;
    for (int w=0;w<8;w++){ S1v[0]+=red[w][0]; S1v[1]+=red[w][1]; S200+=red[w][2]; S201+=red[w][3]; S211+=red[w][4]; }
    float S2[2][2]; S2[0][0]=S200; S2[0][1]=S201; S2[1][0]=S201; S2[1][1]=S211;
    float A[2]={0.f,0.f}, Bc[2]={0.f,0.f}, Cc[2]={0.f,0.f};
    #pragma unroll
    for (int ee=0;ee<2;ee++){
      int h = h2 + 32*ee;
      float th = tvec[h];
      float aq[2],bq[2],ak[2],bk[2],av[2],bv[2],nq[2],nk[2];
      #pragma unroll
      for (int d=0;d<2;d++){
        int cd = 2*h2+d;
        aq[d]=wqkv[cd*6+ee];   bq[d]=bqkv[cd*6+ee];
        ak[d]=wqkv[cd*6+2+ee]; bk[d]=bqkv[cd*6+2+ee];
        av[d]=wqkv[cd*6+4+ee]; bv[d]=bqkv[cd*6+4+ee];
        nq[d]=fmaxf(sqrtf(fmaxf(aq[d]*aq[d]*S2[d][d]+2.f*aq[d]*bq[d]*S1v[d]+bq[d]*bq[d]*1024.f,0.f)),1e-12f);
        nk[d]=fmaxf(sqrtf(fmaxf(ak[d]*ak[d]*S2[d][d]+2.f*ak[d]*bk[d]*S1v[d]+bk[d]*bk[d]*1024.f,0.f)),1e-12f);
      }
      #pragma unroll
      for (int d=0;d<2;d++){
        float l[2];
        #pragma unroll
        for (int e=0;e<2;e++){
          float dot = aq[d]*ak[e]*S2[d][e] + aq[d]*bk[e]*S1v[d] + bq[d]*ak[e]*S1v[e] + bq[d]*bk[e]*1024.f;
          l[e] = dot/(nq[d]*nk[e])*th;
        }
        float mx = fmaxf(l[0],l[1]);
        float p0 = __expf(l[0]-mx), p1 = __expf(l[1]-mx);
        float inv = 1.f/(p0+p1);
        float a0 = p0*inv, a1 = p1*inv;
        int c = 2*h2+d;
        float wfv = wf[c*2+ee];
        A[d]  = fmaf(wfv, a0*av[0], A[d]);
        Bc[d] = fmaf(wfv, a1*av[1], Bc[d]);
        Cc[d] = fmaf(wfv, fmaf(a0,bv[0],a1*bv[1]), Cc[d]);
      }
    }
    coef[0]=A[0]; coef[1]=Bc[0]; coef[2]=Cc[0]+bf[2*h2];
    coef[3]=A[1]; coef[4]=Bc[1]; coef[5]=Cc[1]+bf[2*h2+1];
  }
  __syncthreads();
  float A0=coef[0],B0=coef[1],C0=coef[2],A1=coef[3],B1=coef[4],C1=coef[5];
  float* o0 = g_y5 + (b*64 + h2)*1024;
  float* o1 = g_y5 + (b*64 + 32 + h2)*1024;
  for (int i=t;i<1024;i+=256){
    float a = ch0[i], c = ch1[i];
    o0[i] = fmaf(A0,a,fmaf(B0,c,C0));
    o1[i] = fmaf(A1,a,fmaf(B1,c,C1));
  }
}

// ---------------- K3: spatial attention via Fourier-Bessel moments ----------------
#define NJ 8
__global__ void k_spattn(const float* __restrict__ wqkv, const float* __restrict__ bqkv,
                         const float* __restrict__ tvec){
  int h = blockIdx.x, b = blockIdx.y;
  int ee = h>>5;
  int c0 = (h&31)*2;
  __shared__ float2 qs[1024];
  __shared__ float red[8][44];
  __shared__ float mom[44];
  __shared__ float wj[NJ];
  int t = threadIdx.x;
  if (t < NJ){
    float tt = tvec[h];
    float hx = 0.5f*tt;
    float x2 = hx*hx;
    int j = t;
    float p = 1.f;
    for (int i=0;i<j;i++) p *= hx/(float)(i+1);
    float s = 0.f;
    #pragma unroll
    for (int k=0;k<14;k++){ s += p; p *= x2/((float)(k+1)*(float)(k+1+j)); }
    wj[j] = (j==0?1.f:2.f)*s;
  }
  float aq0=wqkv[c0*6+ee],     bq0=bqkv[c0*6+ee];
  float aq1=wqkv[(c0+1)*6+ee], bq1=bqkv[(c0+1)*6+ee];
  float ak0=wqkv[c0*6+2+ee],     bk0=bqkv[c0*6+2+ee];
  float ak1=wqkv[(c0+1)*6+2+ee], bk1=bqkv[(c0+1)*6+2+ee];
  float av0=wqkv[c0*6+4+ee],     bv0=bqkv[c0*6+4+ee];
  float av1=wqkv[(c0+1)*6+4+ee], bv1=bqkv[(c0+1)*6+4+ee];
  const float* x0p = g_y5 + (b*64 + c0)*1024;
  const float* x1p = x0p + 1024;
  float acc[44];
  #pragma unroll
  for (int v=0;v<44;v++) acc[v]=0.f;
  #pragma unroll
  for (int q=0;q<4;q++){
    int i = t + q*256;
    float x0=x0p[i], x1=x1p[i];
    float qx = fmaf(aq0,x0,bq0), qy = fmaf(aq1,x1,bq1);
    float qi = 1.f/fmaxf(sqrtf(qx*qx+qy*qy),1e-12f);
    qs[i] = make_float2(qx*qi, qy*qi);
    float kx = fmaf(ak0,x0,bk0), ky = fmaf(ak1,x1,bk1);
    float ki = 1.f/fmaxf(sqrtf(kx*kx+ky*ky),1e-12f);
    float c1 = kx*ki, s1 = ky*ki;
    float v0 = fmaf(av0,x0,bv0), v1 = fmaf(av1,x1,bv1);
    acc[0]+=v0; acc[1]+=v1;
    float cj=c1, sj=s1;
    #pragma unroll
    for (int j=1;j<NJ;j++){
      int bse = 2+6*(j-1);
      acc[bse]   += cj;
      acc[bse+1]  = fmaf(cj,v0,acc[bse+1]);
      acc[bse+2]  = fmaf(cj,v1,acc[bse+2]);
      acc[bse+3] += sj;
      acc[bse+4]  = fmaf(sj,v0,acc[bse+4]);
      acc[bse+5]  = fmaf(sj,v1,acc[bse+5]);
      float cn = fmaf(cj,c1,-sj*s1);
      float sn = fmaf(sj,c1, cj*s1);
      cj=cn; sj=sn;
    }
  }
  #pragma unroll
  for (int v=0;v<44;v++){
    float s = acc[v];
    #pragma unroll
    for (int off=16;off;off>>=1) s += __shfl_down_sync(0xffffffffu,s,off);
    if ((t&31)==0) red[t>>5][v] = s;
  }
  __syncthreads();
  if (t<44){
    float s=0.f;
    #pragma unroll
    for (int w=0;w<8;w++) s += red[w][t];
    mom[t]=s;
  }
  __syncthreads();
  float M[44];
  #pragma unroll
  for (int v=0;v<44;v++) M[v]=mom[v];
  float W[NJ];
  #pragma unroll
  for (int j=0;j<NJ;j++) W[j]=wj[j];
  float* ob = g_os + (b*64+h)*2048;
  #pragma unroll
  for (int q=0;q<4;q++){
    int n = t + q*256;
    float2 qq = qs[n];
    float c1=qq.x, s1=qq.y;
    float den = W[0]*1024.f;
    float o0  = W[0]*M[0];
    float o1  = W[0]*M[1];
    float cj=c1, sj=s1;
    #pragma unroll
    for (int j=1;j<NJ;j++){
      int bse = 2+6*(j-1);
      float w = W[j];
      den = fmaf(w, fmaf(cj,M[bse],   sj*M[bse+3]), den);
      o0  = fmaf(w, fmaf(cj,M[bse+1], sj*M[bse+4]), o0);
      o1  = fmaf(w, fmaf(cj,M[bse+2], sj*M[bse+5]), o1);
      float cn = fmaf(cj,c1,-sj*s1);
      float sn = fmaf(sj,c1, cj*s1);
      cj=cn; sj=sn;
    }
    float inv = 1.f/den;
    ob[n]      = o0*inv;
    ob[1024+n] = o1*inv;
  }
}

// ---------------- K4: group fuse + un1 + pixel shuffle + un2 ----------------
// grid (64,2) x 256 thr; block = 16 input positions -> output tile 64ch x 2rows x 32cols.
// Phase C: register micro-GEMM (4 pos x 4 ch per thread), smem-staged coalesced stores.
__global__ void __launch_bounds__(256,1) k_fuse(
                       const float* __restrict__ wf, const float* __restrict__ bf,
                       const float* __restrict__ w1, const float* __restrict__ b1,
                       const float* __restrict__ w2, const float* __restrict__ b2,
                       float* __restrict__ out){
  __shared__ float  y6s[16][64];     // [pos][c]
  __shared__ float  zs[64][36];      // [idx=r*16+pos][cc], padded 36 (conflict-free float4 rows)
  __shared__ float4 w2t4[32][17];    // [q][o/4], padded; transposed un2 weights
  __shared__ float  st[64][64];      // output staging [ch][r1*32 + col]
  int t = threadIdx.x;
  int b = blockIdx.y;
  int n0 = blockIdx.x*16;
  // load w2 (64x32, o-major) transposed into shared: w2f[q*68+o]
  {
    float* w2f = (float*)w2t4;
    for (int i=t;i<2048;i+=256){
      int o = i>>5, q = i&31;
      w2f[q*68 + o] = w2[i];
    }
  }
  // phase A: group fuse -> y6s (16 positions x 64 channels)
  #pragma unroll
  for (int k=0;k<4;k++){
    int j = t + k*256;
    int pos = j&15, c = j>>4;
    int n = n0+pos;
    float o0 = g_os[((b*64 + (c>>1))*2 + (c&1))*1024 + n];
    float o1 = g_os[((b*64 + 32 + (c>>1))*2 + (c&1))*1024 + n];
    y6s[pos][c] = fmaf(wf[c*2],o0, fmaf(wf[c*2+1],o1, bf[c]));
  }
  __syncthreads();
  // phase B: un1 grouped 1x1 -> zs (64 idx x 32 cc)
  #pragma unroll
  for (int k=0;k<8;k++){
    int j = t + k*256;
    int cc = j&31, idx = j>>5;        // idx = r*16+pos
    int r = idx>>4, pos = idx&15;
    int o2 = 4*cc + r;
    zs[idx][cc] = fmaf(w1[o2*2], y6s[pos][2*cc], fmaf(w1[o2*2+1], y6s[pos][2*cc+1], b1[o2]));
  }
  __syncthreads();
  // phase C: 4 idx x 4 ch register tile
  int idxq = t>>4, cg = t&15;         // idxq in [0,16): 4 idx each; cg: channels cg*4..+3
  int idx0 = idxq*4;
  float acc[4][4];
  {
    float b0v=b2[cg*4+0], b1v=b2[cg*4+1], b2v=b2[cg*4+2], b3v=b2[cg*4+3];
    #pragma unroll
    for (int i=0;i<4;i++){ acc[i][0]=b0v; acc[i][1]=b1v; acc[i][2]=b2v; acc[i][3]=b3v; }
  }
  #pragma unroll
  for (int q4=0;q4<8;q4++){
    float4 wq0 = w2t4[q4*4+0][cg];
    float4 wq1 = w2t4[q4*4+1][cg];
    float4 wq2 = w2t4[q4*4+2][cg];
    float4 wq3 = w2t4[q4*4+3][cg];
    #pragma unroll
    for (int i=0;i<4;i++){
      float4 z4 = *(const float4*)&zs[idx0+i][q4*4];
      acc[i][0]=fmaf(z4.x,wq0.x,acc[i][0]); acc[i][1]=fmaf(z4.x,wq0.y,acc[i][1]);
      acc[i][2]=fmaf(z4.x,wq0.z,acc[i][2]); acc[i][3]=fmaf(z4.x,wq0.w,acc[i][3]);
      acc[i][0]=fmaf(z4.y,wq1.x,acc[i][0]); acc[i][1]=fmaf(z4.y,wq1.y,acc[i][1]);
      acc[i][2]=fmaf(z4.y,wq1.z,acc[i][2]); acc[i][3]=fmaf(z4.y,wq1.w,acc[i][3]);
      acc[i][0]=fmaf(z4.z,wq2.x,acc[i][0]); acc[i][1]=fmaf(z4.z,wq2.y,acc[i][1]);
      acc[i][2]=fmaf(z4.z,wq2.z,acc[i][2]); acc[i][3]=fmaf(z4.z,wq2.w,acc[i][3]);
      acc[i][0]=fmaf(z4.w,wq3.x,acc[i][0]); acc[i][1]=fmaf(z4.w,wq3.y,acc[i][1]);
      acc[i][2]=fmaf(z4.w,wq3.z,acc[i][2]); acc[i][3]=fmaf(z4.w,wq3.w,acc[i][3]);
    }
  }
  // stage to smem in output-tile layout
  #pragma unroll
  for (int i=0;i<4;i++){
    int idx = idx0+i;
    int r = idx>>4, pos = idx&15;
    int r1 = r>>1, r2 = r&1;
    int col = pos*2 + r2;
    #pragma unroll
    for (int j=0;j<4;j++)
      st[cg*4+j][r1*32 + col] = acc[i][j];
  }
  __syncthreads();
  // coalesced write: 64ch x 2rows x 32cols = 1024 float4
  int hh = n0>>5;
  int ww0 = n0&31;
  float* ob = out + (b<<18) + ((2*hh)<<6) + 2*ww0;
  #pragma unroll
  for (int k=0;k<4;k++){
    int flat = t + k*256;            // float4 index
    int ch = flat>>4;
    int r1 = (flat>>3)&1;
    int colq = flat&7;
    float4 v = *(const float4*)&st[ch][r1*32 + colq*4];
    *(float4*)&ob[(ch<<12) + (r1<<6) + colq*4] = v;
  }
}

extern "C" void kernel_launch(void* const* d_in, const int* in_sizes, int n_in,
                              void* d_out, int out_size){
  const float* x       = (const float*)d_in[0];
  const float* w_sq1   = (const float*)d_in[1];
  const float* b_sq1   = (const float*)d_in[2];
  const float* w_sq2   = (const float*)d_in[3];
  const float* b_sq2   = (const float*)d_in[4];
  const float* ca_wqkv = (const float*)d_in[5];
  const float* ca_bqkv = (const float*)d_in[6];
  const float* ca_t    = (const float*)d_in[7];
  const float* ca_wf   = (const float*)d_in[8];
  const float* ca_bf   = (const float*)d_in[9];
  const float* sa_wqkv = (const float*)d_in[10];
  const float* sa_bqkv = (const float*)d_in[11];
  const float* sa_t    = (const float*)d_in[12];
  const float* sa_wf   = (const float*)d_in[13];
  const float* sa_bf   = (const float*)d_in[14];
  const float* w_un1   = (const float*)d_in[15];
  const float* b_un1   = (const float*)d_in[16];
  const float* w_un2   = (const float*)d_in[17];
  const float* b_un2   = (const float*)d_in[18];
  float* out = (float*)d_out;

  k_squeeze1<<<dim3(16,4,2),256>>>(x, w_sq1, b_sq1);
  k_chattn<<<dim3(32,2),256>>>(w_sq2, b_sq2, ca_wqkv, ca_bqkv, ca_t, ca_wf, ca_bf);
  k_spattn<<<dim3(64,2),256>>>(sa_wqkv, sa_bqkv, sa_t);
  k_fuse<<<dim3(64,2),256>>>(sa_wf, sa_bf, w_un1, b_un1, w_un2, b_un2, out);
}

// round 7
// speedup vs baseline: 1.5444x; 1.5444x over previous
#include <cuda_runtime.h>

// ---------------- scratch (no allocations allowed) ----------------
__device__ float g_y3[2*64*1024];      // after squeeze+depthwise+perm (b,64,32,32)
__device__ float g_y5[2*64*1024];      // after channel attn + nidx perm
__device__ float g_os[2*64*2*1024];    // spatial attn output per head (b,h,d,n)

// ---------------- K1: pointwise squeeze 64->32 + depthwise 2x2 s2 + perm -> y3 ----------------
__global__ void k_squeeze(const float* __restrict__ x, const float* __restrict__ w,
                          const float* __restrict__ bias,
                          const float* __restrict__ w2, const float* __restrict__ b2){
  __shared__ float ws[512];
  __shared__ float y1s[8][256];
  int t = threadIdx.x;
  int bx = blockIdx.x, og = blockIdx.y, b = blockIdx.z;
  for (int i=t;i<512;i+=256) ws[i] = w[og*512 + i];
  __syncthreads();
  int pos = bx*256 + t;
  float acc[8];
  #pragma unroll
  for (int oo=0;oo<8;oo++) acc[oo] = bias[og*8+oo];
  const float* xp = x + b*262144 + pos;
  #pragma unroll 4
  for (int c=0;c<64;c++){
    float xv = xp[c<<12];
    #pragma unroll
    for (int oo=0;oo<8;oo++) acc[oo] = fmaf(xv, ws[oo*64+c], acc[oo]);
  }
  #pragma unroll
  for (int oo=0;oo<8;oo++) y1s[oo][t] = acc[oo];
  __syncthreads();
  // depthwise: 16 oc-locals x 64 positions = 1024 outputs, 4 per thread
  #pragma unroll
  for (int k=0;k<4;k++){
    int j = t + k*256;
    int ocl = j>>6, p2 = j&63;
    int gg = ocl>>1, dd = ocl&1;
    int oc = 2*(og*8+gg) + dd;
    int hl = p2>>5, wc = p2&31;
    float w0=w2[oc*4], w1=w2[oc*4+1], w2v=w2[oc*4+2], w3=w2[oc*4+3];
    int base = (hl<<7) + (wc<<1);
    float val = b2[oc] + y1s[gg][base]*w0 + y1s[gg][base+1]*w1
                       + y1s[gg][base+64]*w2v + y1s[gg][base+65]*w3;
    int n = ((2*bx + hl)<<5) + wc;
    int p = ((oc&31)<<1) | (oc>>5);          // idx permutation
    g_y3[((b*64+p)<<10) + n] = val;
  }
}

// ---------------- K2: channel attention via moments (clean float4 loads) ----------------
__global__ void k_chattn(const float* __restrict__ wqkv, const float* __restrict__ bqkv,
                         const float* __restrict__ tvec, const float* __restrict__ wf,
                         const float* __restrict__ bf){
  int h2 = blockIdx.x, b = blockIdx.y;       // h2 in [0,32)
  __shared__ float ch0[1024], ch1[1024];
  __shared__ float red[8][5];
  __shared__ float coef[6];
  int t = threadIdx.x;
  const float4* c0p = (const float4*)(g_y3 + ((b*64 + 2*h2)<<10));
  const float4* c1p = c0p + 256;
  float4 a4 = c0p[t], c4 = c1p[t];
  ((float4*)ch0)[t] = a4;
  ((float4*)ch1)[t] = c4;
  float s0 = a4.x+a4.y+a4.z+a4.w;
  float s1 = c4.x+c4.y+c4.z+c4.w;
  float m00 = a4.x*a4.x + a4.y*a4.y + a4.z*a4.z + a4.w*a4.w;
  float m01 = a4.x*c4.x + a4.y*c4.y + a4.z*c4.z + a4.w*c4.w;
  float m11 = c4.x*c4.x + c4.y*c4.y + c4.z*c4.z + c4.w*c4.w;
  #pragma unroll
  for (int off=16;off;off>>=1){
    s0 += __shfl_down_sync(0xffffffffu,s0,off);
    s1 += __shfl_down_sync(0xffffffffu,s1,off);
    m00+= __shfl_down_sync(0xffffffffu,m00,off);
    m01+= __shfl_down_sync(0xffffffffu,m01,off);
    m11+= __shfl_down_sync(0xffffffffu,m11,off);
  }
  if ((t&31)==0){ int w=t>>5; red[w][0]=s0; red[w][1]=s1; red[w][2]=m00; red[w][3]=m01; red[w][4]=m11; }
  __syncthreads();
  if (t==0){
    float S1v[2]={0.f,0.f}, S200=0.f,S201=0.f,S211=0.f;
    for (int w=0;w<8;w++){ S1v[0]+=red[w][0]; S1v[1]+=red[w][1]; S200+=red[w][2]; S201+=red[w][3]; S211+=red[w][4]; }
    float S2[2][2]; S2[0][0]=S200; S2[0][1]=S201; S2[1][0]=S201; S2[1][1]=S211;
    float A[2]={0.f,0.f}, Bc[2]={0.f,0.f}, Cc[2]={0.f,0.f};
    #pragma unroll
    for (int ee=0;ee<2;ee++){
      int h = h2 + 32*ee;
      float th = tvec[h];
      float aq[2],bq[2],ak[2],bk[2],av[2],bv[2],nq[2],nk[2];
      #pragma unroll
      for (int d=0;d<2;d++){
        int cd = 2*h2+d;
        aq[d]=wqkv[cd*6+ee];   bq[d]=bqkv[cd*6+ee];
        ak[d]=wqkv[cd*6+2+ee]; bk[d]=bqkv[cd*6+2+ee];
        av[d]=wqkv[cd*6+4+ee]; bv[d]=bqkv[cd*6+4+ee];
        nq[d]=fmaxf(sqrtf(fmaxf(aq[d]*aq[d]*S2[d][d]+2.f*aq[d]*bq[d]*S1v[d]+bq[d]*bq[d]*1024.f,0.f)),1e-12f);
        nk[d]=fmaxf(sqrtf(fmaxf(ak[d]*ak[d]*S2[d][d]+2.f*ak[d]*bk[d]*S1v[d]+bk[d]*bk[d]*1024.f,0.f)),1e-12f);
      }
      #pragma unroll
      for (int d=0;d<2;d++){
        float l[2];
        #pragma unroll
        for (int e=0;e<2;e++){
          float dot = aq[d]*ak[e]*S2[d][e] + aq[d]*bk[e]*S1v[d] + bq[d]*ak[e]*S1v[e] + bq[d]*bk[e]*1024.f;
          l[e] = dot/(nq[d]*nk[e])*th;
        }
        float mx = fmaxf(l[0],l[1]);
        float p0 = __expf(l[0]-mx), p1 = __expf(l[1]-mx);
        float inv = 1.f/(p0+p1);
        float a0 = p0*inv, a1 = p1*inv;
        int c = 2*h2+d;
        float wfv = wf[c*2+ee];
        A[d]  = fmaf(wfv, a0*av[0], A[d]);
        Bc[d] = fmaf(wfv, a1*av[1], Bc[d]);
        Cc[d] = fmaf(wfv, fmaf(a0,bv[0],a1*bv[1]), Cc[d]);
      }
    }
    coef[0]=A[0]; coef[1]=Bc[0]; coef[2]=Cc[0]+bf[2*h2];
    coef[3]=A[1]; coef[4]=Bc[1]; coef[5]=Cc[1]+bf[2*h2+1];
  }
  __syncthreads();
  float A0=coef[0],B0=coef[1],C0=coef[2],A1=coef[3],B1=coef[4],C1=coef[5];
  float* o0 = g_y5 + (b*64 + h2)*1024;
  float* o1 = g_y5 + (b*64 + 32 + h2)*1024;
  for (int i=t;i<1024;i+=256){
    float a = ch0[i], c = ch1[i];
    o0[i] = fmaf(A0,a,fmaf(B0,c,C0));
    o1[i] = fmaf(A1,a,fmaf(B1,c,C1));
  }
}

// ---------------- K3: spatial attention via Fourier-Bessel moments (NJ=6, 32 moments) ----------------
#define NJ 6
__global__ void k_spattn(const float* __restrict__ wqkv, const float* __restrict__ bqkv,
                         const float* __restrict__ tvec){
  int h = blockIdx.x, b = blockIdx.y;
  int ee = h>>5;
  int c0 = (h&31)*2;
  __shared__ float2 qs[1024];
  __shared__ float red[8][32];
  __shared__ float mom[32];
  __shared__ float wj[NJ];
  int t = threadIdx.x;
  int lane = t&31, wid = t>>5;
  if (t < NJ){
    float tt = tvec[h];
    float hx = 0.5f*tt;
    float x2 = hx*hx;
    int j = t;
    float p = 1.f;
    for (int i=0;i<j;i++) p *= hx/(float)(i+1);
    float s = 0.f;
    #pragma unroll
    for (int k=0;k<14;k++){ s += p; p *= x2/((float)(k+1)*(float)(k+1+j)); }
    wj[j] = (j==0?1.f:2.f)*s;
  }
  float aq0=wqkv[c0*6+ee],     bq0=bqkv[c0*6+ee];
  float aq1=wqkv[(c0+1)*6+ee], bq1=bqkv[(c0+1)*6+ee];
  float ak0=wqkv[c0*6+2+ee],     bk0=bqkv[c0*6+2+ee];
  float ak1=wqkv[(c0+1)*6+2+ee], bk1=bqkv[(c0+1)*6+2+ee];
  float av0=wqkv[c0*6+4+ee],     bv0=bqkv[c0*6+4+ee];
  float av1=wqkv[(c0+1)*6+4+ee], bv1=bqkv[(c0+1)*6+4+ee];
  const float* x0p = g_y5 + (b*64 + c0)*1024;
  const float* x1p = x0p + 1024;
  // moments: [0]=Sum v0, [1]=Sum v1; j=1..5 base=2+6*(j-1): c, c*v0, c*v1, s, s*v0, s*v1
  float acc[32];
  #pragma unroll
  for (int v=0;v<32;v++) acc[v]=0.f;
  #pragma unroll
  for (int q=0;q<4;q++){
    int i = t + q*256;
    float x0=x0p[i], x1=x1p[i];
    float qx = fmaf(aq0,x0,bq0), qy = fmaf(aq1,x1,bq1);
    float qi = rsqrtf(fmaxf(qx*qx+qy*qy,1e-24f));
    qs[i] = make_float2(qx*qi, qy*qi);
    float kx = fmaf(ak0,x0,bk0), ky = fmaf(ak1,x1,bk1);
    float ki = rsqrtf(fmaxf(kx*kx+ky*ky,1e-24f));
    float c1 = kx*ki, s1 = ky*ki;
    float v0 = fmaf(av0,x0,bv0), v1 = fmaf(av1,x1,bv1);
    acc[0]+=v0; acc[1]+=v1;
    float cj=c1, sj=s1;
    #pragma unroll
    for (int j=1;j<NJ;j++){
      int bse = 2+6*(j-1);
      acc[bse]   += cj;
      acc[bse+1]  = fmaf(cj,v0,acc[bse+1]);
      acc[bse+2]  = fmaf(cj,v1,acc[bse+2]);
      acc[bse+3] += sj;
      acc[bse+4]  = fmaf(sj,v0,acc[bse+4]);
      acc[bse+5]  = fmaf(sj,v1,acc[bse+5]);
      float cn = fmaf(cj,c1,-sj*s1);
      float sn = fmaf(sj,c1, cj*s1);
      cj=cn; sj=sn;
    }
  }
  // multi-value warp butterfly: 31 SHFL total; lane ends holding moment 'lane'
  #pragma unroll
  for (int o=16;o;o>>=1){
    bool hi = (lane & o)!=0;
    #pragma unroll
    for (int i=0;i<o;i++){
      float keep = hi ? acc[i+o] : acc[i];
      float send = hi ? acc[i]   : acc[i+o];
      float recv = __shfl_xor_sync(0xffffffffu, send, o);
      acc[i] = keep + recv;
    }
  }
  red[wid][lane] = acc[0];
  __syncthreads();
  if (t<32){
    float s=0.f;
    #pragma unroll
    for (int w=0;w<8;w++) s += red[w][t];
    mom[t]=s;
  }
  __syncthreads();
  float M[32];
  #pragma unroll
  for (int v=0;v<32;v++) M[v]=mom[v];
  float W[NJ];
  #pragma unroll
  for (int j=0;j<NJ;j++) W[j]=wj[j];
  float* ob = g_os + (b*64+h)*2048;
  #pragma unroll
  for (int q=0;q<4;q++){
    int n = t + q*256;
    float2 qq = qs[n];
    float c1=qq.x, s1=qq.y;
    float den = W[0]*1024.f;
    float o0  = W[0]*M[0];
    float o1  = W[0]*M[1];
    float cj=c1, sj=s1;
    #pragma unroll
    for (int j=1;j<NJ;j++){
      int bse = 2+6*(j-1);
      float w = W[j];
      den = fmaf(w, fmaf(cj,M[bse],   sj*M[bse+3]), den);
      o0  = fmaf(w, fmaf(cj,M[bse+1], sj*M[bse+4]), o0);
      o1  = fmaf(w, fmaf(cj,M[bse+2], sj*M[bse+5]), o1);
      float cn = fmaf(cj,c1,-sj*s1);
      float sn = fmaf(sj,c1, cj*s1);
      cj=cn; sj=sn;
    }
    float inv = 1.f/den;
    ob[n]      = o0*inv;
    ob[1024+n] = o1*inv;
  }
}

// ---------------- K4: group fuse + un1 + pixel shuffle + un2 (R3 variant — best wall) ----------------
__global__ void k_fuse(const float* __restrict__ wf, const float* __restrict__ bf,
                       const float* __restrict__ w1, const float* __restrict__ b1,
                       const float* __restrict__ w2, const float* __restrict__ b2,
                       float* __restrict__ out){
  __shared__ float  y6s[16][64];     // [pos][c]
  __shared__ float  zs[64][33];      // [idx = r*16+pos][cc], padded
  __shared__ float4 w2t4[32][17];    // [q][o/4], padded; transposed un2 weights
  int t = threadIdx.x;
  int b = blockIdx.y;
  int n0 = blockIdx.x*16;
  {
    float* w2f = (float*)w2t4;       // index: q*68 + o
    for (int i=t;i<2048;i+=256){
      int o = i>>5, q = i&31;
      w2f[q*68 + o] = w2[i];
    }
  }
  for (int j=t;j<1024;j+=256){
    int pos = j&15, c = j>>4;
    int n = n0+pos;
    float o0 = g_os[((b*64 + (c>>1))*2 + (c&1))*1024 + n];
    float o1 = g_os[((b*64 + 32 + (c>>1))*2 + (c&1))*1024 + n];
    y6s[pos][c] = fmaf(wf[c*2],o0, fmaf(wf[c*2+1],o1, bf[c]));
  }
  __syncthreads();
  for (int j=t;j<2048;j+=256){
    int cc = j&31, idx = j>>5;        // idx = r*16+pos
    int r = idx>>4, pos = idx&15;
    int o2 = 4*cc + r;
    zs[idx][cc] = fmaf(w1[o2*2], y6s[pos][2*cc], fmaf(w1[o2*2+1], y6s[pos][2*cc+1], b1[o2]));
  }
  __syncthreads();
  int og = t>>6, idx = t&63;
  int r = idx>>4, pos = idx&15;
  float acc[16];
  #pragma unroll
  for (int oo=0;oo<16;oo++) acc[oo] = b2[og*16+oo];
  #pragma unroll 4
  for (int q=0;q<32;q++){
    float zq = zs[idx][q];
    #pragma unroll
    for (int k4=0;k4<4;k4++){
      float4 wv = w2t4[q][og*4 + k4];
      acc[k4*4+0] = fmaf(zq, wv.x, acc[k4*4+0]);
      acc[k4*4+1] = fmaf(zq, wv.y, acc[k4*4+1]);
      acc[k4*4+2] = fmaf(zq, wv.z, acc[k4*4+2]);
      acc[k4*4+3] = fmaf(zq, wv.w, acc[k4*4+3]);
    }
  }
  int n = n0+pos;
  int hh = n>>5, ww = n&31;
  float* outp = out + (b<<18) + ((2*hh + (r>>1))<<6) + 2*ww + (r&1);
  #pragma unroll
  for (int oo=0;oo<16;oo++)
    outp[(og*16+oo)<<12] = acc[oo];
}

extern "C" void kernel_launch(void* const* d_in, const int* in_sizes, int n_in,
                              void* d_out, int out_size){
  const float* x       = (const float*)d_in[0];
  const float* w_sq1   = (const float*)d_in[1];
  const float* b_sq1   = (const float*)d_in[2];
  const float* w_sq2   = (const float*)d_in[3];
  const float* b_sq2   = (const float*)d_in[4];
  const float* ca_wqkv = (const float*)d_in[5];
  const float* ca_bqkv = (const float*)d_in[6];
  const float* ca_t    = (const float*)d_in[7];
  const float* ca_wf   = (const float*)d_in[8];
  const float* ca_bf   = (const float*)d_in[9];
  const float* sa_wqkv = (const float*)d_in[10];
  const float* sa_bqkv = (const float*)d_in[11];
  const float* sa_t    = (const float*)d_in[12];
  const float* sa_wf   = (const float*)d_in[13];
  const float* sa_bf   = (const float*)d_in[14];
  const float* w_un1   = (const float*)d_in[15];
  const float* b_un1   = (const float*)d_in[16];
  const float* w_un2   = (const float*)d_in[17];
  const float* b_un2   = (const float*)d_in[18];
  float* out = (float*)d_out;

  k_squeeze<<<dim3(16,4,2),256>>>(x, w_sq1, b_sq1, w_sq2, b_sq2);
  k_chattn<<<dim3(32,2),256>>>(ca_wqkv, ca_bqkv, ca_t, ca_wf, ca_bf);
  k_spattn<<<dim3(64,2),256>>>(sa_wqkv, sa_bqkv, sa_t);
  k_fuse<<<dim3(64,2),256>>>(sa_wf, sa_bf, w_un1, b_un1, w_un2, b_un2, out);
}

// round 8
// speedup vs baseline: 1.5487x; 1.0028x over previous
#include <cuda_runtime.h>

// ---------------- scratch (no allocations allowed) ----------------
__device__ float g_y3[2*64*1024];      // after squeeze+depthwise+perm (b,64,32,32)
__device__ float g_y5[2*64*1024];      // after channel attn + nidx perm
__device__ float g_os[2*64*2*1024];    // spatial attn output per head (b,h,d,n)

// ---------------- K1: pointwise squeeze 64->32 + depthwise 2x2 s2 + perm -> y3 ----------------
__global__ void k_squeeze(const float* __restrict__ x, const float* __restrict__ w,
                          const float* __restrict__ bias,
                          const float* __restrict__ w2, const float* __restrict__ b2){
  __shared__ float ws[512];
  __shared__ float y1s[8][256];
  int t = threadIdx.x;
  int bx = blockIdx.x, og = blockIdx.y, b = blockIdx.z;
  for (int i=t;i<512;i+=256) ws[i] = w[og*512 + i];
  __syncthreads();
  int pos = bx*256 + t;
  float acc[8];
  #pragma unroll
  for (int oo=0;oo<8;oo++) acc[oo] = bias[og*8+oo];
  const float* xp = x + b*262144 + pos;
  #pragma unroll 4
  for (int c=0;c<64;c++){
    float xv = xp[c<<12];
    #pragma unroll
    for (int oo=0;oo<8;oo++) acc[oo] = fmaf(xv, ws[oo*64+c], acc[oo]);
  }
  #pragma unroll
  for (int oo=0;oo<8;oo++) y1s[oo][t] = acc[oo];
  __syncthreads();
  // depthwise: 16 oc-locals x 64 positions = 1024 outputs, 4 per thread
  #pragma unroll
  for (int k=0;k<4;k++){
    int j = t + k*256;
    int ocl = j>>6, p2 = j&63;
    int gg = ocl>>1, dd = ocl&1;
    int oc = 2*(og*8+gg) + dd;
    int hl = p2>>5, wc = p2&31;
    float w0=w2[oc*4], w1=w2[oc*4+1], w2v=w2[oc*4+2], w3=w2[oc*4+3];
    int base = (hl<<7) + (wc<<1);
    float val = b2[oc] + y1s[gg][base]*w0 + y1s[gg][base+1]*w1
                       + y1s[gg][base+64]*w2v + y1s[gg][base+65]*w3;
    int n = ((2*bx + hl)<<5) + wc;
    int p = ((oc&31)<<1) | (oc>>5);          // idx permutation
    g_y3[((b*64+p)<<10) + n] = val;
  }
}

// ---------------- K2: channel attention via moments (clean float4 loads) ----------------
__global__ void k_chattn(const float* __restrict__ wqkv, const float* __restrict__ bqkv,
                         const float* __restrict__ tvec, const float* __restrict__ wf,
                         const float* __restrict__ bf){
  int h2 = blockIdx.x, b = blockIdx.y;       // h2 in [0,32)
  __shared__ float ch0[1024], ch1[1024];
  __shared__ float red[8][5];
  __shared__ float coef[6];
  int t = threadIdx.x;
  const float4* c0p = (const float4*)(g_y3 + ((b*64 + 2*h2)<<10));
  const float4* c1p = c0p + 256;
  float4 a4 = c0p[t], c4 = c1p[t];
  ((float4*)ch0)[t] = a4;
  ((float4*)ch1)[t] = c4;
  float s0 = a4.x+a4.y+a4.z+a4.w;
  float s1 = c4.x+c4.y+c4.z+c4.w;
  float m00 = a4.x*a4.x + a4.y*a4.y + a4.z*a4.z + a4.w*a4.w;
  float m01 = a4.x*c4.x + a4.y*c4.y + a4.z*c4.z + a4.w*c4.w;
  float m11 = c4.x*c4.x + c4.y*c4.y + c4.z*c4.z + c4.w*c4.w;
  #pragma unroll
  for (int off=16;off;off>>=1){
    s0 += __shfl_down_sync(0xffffffffu,s0,off);
    s1 += __shfl_down_sync(0xffffffffu,s1,off);
    m00+= __shfl_down_sync(0xffffffffu,m00,off);
    m01+= __shfl_down_sync(0xffffffffu,m01,off);
    m11+= __shfl_down_sync(0xffffffffu,m11,off);
  }
  if ((t&31)==0){ int w=t>>5; red[w][0]=s0; red[w][1]=s1; red[w][2]=m00; red[w][3]=m01; red[w][4]=m11; }
  __syncthreads();
  if (t==0){
    float S1v[2]={0.f,0.f}, S200=0.f,S201=0.f,S211=0.f;
    for (int w=0;w<8;w++){ S1v[0]+=red[w][0]; S1v[1]+=red[w][1]; S200+=red[w][2]; S201+=red[w][3]; S211+=red[w][4]; }
    float S2[2][2]; S2[0][0]=S200; S2[0][1]=S201; S2[1][0]=S201; S2[1][1]=S211;
    float A[2]={0.f,0.f}, Bc[2]={0.f,0.f}, Cc[2]={0.f,0.f};
    #pragma unroll
    for (int ee=0;ee<2;ee++){
      int h = h2 + 32*ee;
      float th = tvec[h];
      float aq[2],bq[2],ak[2],bk[2],av[2],bv[2],nq[2],nk[2];
      #pragma unroll
      for (int d=0;d<2;d++){
        int cd = 2*h2+d;
        aq[d]=wqkv[cd*6+ee];   bq[d]=bqkv[cd*6+ee];
        ak[d]=wqkv[cd*6+2+ee]; bk[d]=bqkv[cd*6+2+ee];
        av[d]=wqkv[cd*6+4+ee]; bv[d]=bqkv[cd*6+4+ee];
        nq[d]=fmaxf(sqrtf(fmaxf(aq[d]*aq[d]*S2[d][d]+2.f*aq[d]*bq[d]*S1v[d]+bq[d]*bq[d]*1024.f,0.f)),1e-12f);
        nk[d]=fmaxf(sqrtf(fmaxf(ak[d]*ak[d]*S2[d][d]+2.f*ak[d]*bk[d]*S1v[d]+bk[d]*bk[d]*1024.f,0.f)),1e-12f);
      }
      #pragma unroll
      for (int d=0;d<2;d++){
        float l[2];
        #pragma unroll
        for (int e=0;e<2;e++){
          float dot = aq[d]*ak[e]*S2[d][e] + aq[d]*bk[e]*S1v[d] + bq[d]*ak[e]*S1v[e] + bq[d]*bk[e]*1024.f;
          l[e] = dot/(nq[d]*nk[e])*th;
        }
        float mx = fmaxf(l[0],l[1]);
        float p0 = __expf(l[0]-mx), p1 = __expf(l[1]-mx);
        float inv = 1.f/(p0+p1);
        float a0 = p0*inv, a1 = p1*inv;
        int c = 2*h2+d;
        float wfv = wf[c*2+ee];
        A[d]  = fmaf(wfv, a0*av[0], A[d]);
        Bc[d] = fmaf(wfv, a1*av[1], Bc[d]);
        Cc[d] = fmaf(wfv, fmaf(a0,bv[0],a1*bv[1]), Cc[d]);
      }
    }
    coef[0]=A[0]; coef[1]=Bc[0]; coef[2]=Cc[0]+bf[2*h2];
    coef[3]=A[1]; coef[4]=Bc[1]; coef[5]=Cc[1]+bf[2*h2+1];
  }
  __syncthreads();
  float A0=coef[0],B0=coef[1],C0=coef[2],A1=coef[3],B1=coef[4],C1=coef[5];
  float* o0 = g_y5 + (b*64 + h2)*1024;
  float* o1 = g_y5 + (b*64 + 32 + h2)*1024;
  for (int i=t;i<1024;i+=256){
    float a = ch0[i], c = ch1[i];
    o0[i] = fmaf(A0,a,fmaf(B0,c,C0));
    o1[i] = fmaf(A1,a,fmaf(B1,c,C1));
  }
}

// ---------------- K3: spatial attention via Fourier-Bessel moments (NJ=6, 32 moments) ----------------
#define NJ 6
__global__ void k_spattn(const float* __restrict__ wqkv, const float* __restrict__ bqkv,
                         const float* __restrict__ tvec){
  int h = blockIdx.x, b = blockIdx.y;
  int ee = h>>5;
  int c0 = (h&31)*2;
  __shared__ float2 qs[1024];
  __shared__ float red[8][32];
  __shared__ float mom[32];
  __shared__ float wj[NJ];
  int t = threadIdx.x;
  int lane = t&31, wid = t>>5;
  if (t < NJ){
    float tt = tvec[h];
    float hx = 0.5f*tt;
    float x2 = hx*hx;
    int j = t;
    float p = 1.f;
    for (int i=0;i<j;i++) p *= hx/(float)(i+1);
    float s = 0.f;
    #pragma unroll
    for (int k=0;k<14;k++){ s += p; p *= x2/((float)(k+1)*(float)(k+1+j)); }
    wj[j] = (j==0?1.f:2.f)*s;
  }
  float aq0=wqkv[c0*6+ee],     bq0=bqkv[c0*6+ee];
  float aq1=wqkv[(c0+1)*6+ee], bq1=bqkv[(c0+1)*6+ee];
  float ak0=wqkv[c0*6+2+ee],     bk0=bqkv[c0*6+2+ee];
  float ak1=wqkv[(c0+1)*6+2+ee], bk1=bqkv[(c0+1)*6+2+ee];
  float av0=wqkv[c0*6+4+ee],     bv0=bqkv[c0*6+4+ee];
  float av1=wqkv[(c0+1)*6+4+ee], bv1=bqkv[(c0+1)*6+4+ee];
  const float* x0p = g_y5 + (b*64 + c0)*1024;
  const float* x1p = x0p + 1024;
  float acc[32];
  #pragma unroll
  for (int v=0;v<32;v++) acc[v]=0.f;
  #pragma unroll
  for (int q=0;q<4;q++){
    int i = t + q*256;
    float x0=x0p[i], x1=x1p[i];
    float qx = fmaf(aq0,x0,bq0), qy = fmaf(aq1,x1,bq1);
    float qi = rsqrtf(fmaxf(qx*qx+qy*qy,1e-24f));
    qs[i] = make_float2(qx*qi, qy*qi);
    float kx = fmaf(ak0,x0,bk0), ky = fmaf(ak1,x1,bk1);
    float ki = rsqrtf(fmaxf(kx*kx+ky*ky,1e-24f));
    float c1 = kx*ki, s1 = ky*ki;
    float v0 = fmaf(av0,x0,bv0), v1 = fmaf(av1,x1,bv1);
    acc[0]+=v0; acc[1]+=v1;
    float cj=c1, sj=s1;
    #pragma unroll
    for (int j=1;j<NJ;j++){
      int bse = 2+6*(j-1);
      acc[bse]   += cj;
      acc[bse+1]  = fmaf(cj,v0,acc[bse+1]);
      acc[bse+2]  = fmaf(cj,v1,acc[bse+2]);
      acc[bse+3] += sj;
      acc[bse+4]  = fmaf(sj,v0,acc[bse+4]);
      acc[bse+5]  = fmaf(sj,v1,acc[bse+5]);
      float cn = fmaf(cj,c1,-sj*s1);
      float sn = fmaf(sj,c1, cj*s1);
      cj=cn; sj=sn;
    }
  }
  // multi-value warp butterfly: 31 SHFL total; lane ends holding moment 'lane'
  #pragma unroll
  for (int o=16;o;o>>=1){
    bool hi = (lane & o)!=0;
    #pragma unroll
    for (int i=0;i<o;i++){
      float keep = hi ? acc[i+o] : acc[i];
      float send = hi ? acc[i]   : acc[i+o];
      float recv = __shfl_xor_sync(0xffffffffu, send, o);
      acc[i] = keep + recv;
    }
  }
  red[wid][lane] = acc[0];
  __syncthreads();
  if (t<32){
    float s=0.f;
    #pragma unroll
    for (int w=0;w<8;w++) s += red[w][t];
    mom[t]=s;
  }
  __syncthreads();
  float M[32];
  #pragma unroll
  for (int v=0;v<32;v++) M[v]=mom[v];
  float W[NJ];
  #pragma unroll
  for (int j=0;j<NJ;j++) W[j]=wj[j];
  float* ob = g_os + (b*64+h)*2048;
  #pragma unroll
  for (int q=0;q<4;q++){
    int n = t + q*256;
    float2 qq = qs[n];
    float c1=qq.x, s1=qq.y;
    float den = W[0]*1024.f;
    float o0  = W[0]*M[0];
    float o1  = W[0]*M[1];
    float cj=c1, sj=s1;
    #pragma unroll
    for (int j=1;j<NJ;j++){
      int bse = 2+6*(j-1);
      float w = W[j];
      den = fmaf(w, fmaf(cj,M[bse],   sj*M[bse+3]), den);
      o0  = fmaf(w, fmaf(cj,M[bse+1], sj*M[bse+4]), o0);
      o1  = fmaf(w, fmaf(cj,M[bse+2], sj*M[bse+5]), o1);
      float cn = fmaf(cj,c1,-sj*s1);
      float sn = fmaf(sj,c1, cj*s1);
      cj=cn; sj=sn;
    }
    float inv = 1.f/den;
    ob[n]      = o0*inv;
    ob[1024+n] = o1*inv;
  }
}

// ---------------- K4: group fuse + un1 + pixel shuffle + un2 (tile=8 pos, 2 CTAs/SM) ----------------
__global__ void __launch_bounds__(256,2) k_fuse(
                       const float* __restrict__ wf, const float* __restrict__ bf,
                       const float* __restrict__ w1, const float* __restrict__ b1,
                       const float* __restrict__ w2, const float* __restrict__ b2,
                       float* __restrict__ out){
  __shared__ float  y6s[8][64];      // [pos][c]
  __shared__ float  zs[32][33];      // [idx = r*8+pos][cc], padded
  __shared__ float4 w2t4[32][17];    // [q][o/4], padded; transposed un2 weights
  int t = threadIdx.x;
  int b = blockIdx.y;
  int n0 = blockIdx.x*8;
  {
    float* w2f = (float*)w2t4;       // index: q*68 + o
    for (int i=t;i<2048;i+=256){
      int o = i>>5, q = i&31;
      w2f[q*68 + o] = w2[i];
    }
  }
  // phase A: group fuse -> y6s (8 positions x 64 channels), 2 per thread
  #pragma unroll
  for (int k=0;k<2;k++){
    int j = t + k*256;
    int pos = j&7, c = j>>3;
    int n = n0+pos;
    float o0 = g_os[((b*64 + (c>>1))*2 + (c&1))*1024 + n];
    float o1 = g_os[((b*64 + 32 + (c>>1))*2 + (c&1))*1024 + n];
    y6s[pos][c] = fmaf(wf[c*2],o0, fmaf(wf[c*2+1],o1, bf[c]));
  }
  __syncthreads();
  // phase B: un1 grouped 1x1 -> zs (32 idx x 32 cc), 4 per thread
  #pragma unroll
  for (int k=0;k<4;k++){
    int j = t + k*256;
    int cc = j&31, idx = j>>5;        // idx = r*8+pos
    int r = idx>>3, pos = idx&7;
    int o2 = 4*cc + r;
    zs[idx][cc] = fmaf(w1[o2*2], y6s[pos][2*cc], fmaf(w1[o2*2+1], y6s[pos][2*cc+1], b1[o2]));
  }
  __syncthreads();
  // phase C: 8 channels per thread (acc[8]), idx shared by 8 threads (broadcast LDS)
  int og = t>>5, idx = t&31;          // og in [0,8): channels og*8..og*8+7
  int r = idx>>3, pos = idx&7;
  float acc[8];
  #pragma unroll
  for (int oo=0;oo<8;oo++) acc[oo] = b2[og*8+oo];
  #pragma unroll 4
  for (int q=0;q<32;q++){
    float zq = zs[idx][q];
    float4 wv0 = w2t4[q][og*2+0];
    float4 wv1 = w2t4[q][og*2+1];
    acc[0] = fmaf(zq, wv0.x, acc[0]);
    acc[1] = fmaf(zq, wv0.y, acc[1]);
    acc[2] = fmaf(zq, wv0.z, acc[2]);
    acc[3] = fmaf(zq, wv0.w, acc[3]);
    acc[4] = fmaf(zq, wv1.x, acc[4]);
    acc[5] = fmaf(zq, wv1.y, acc[5]);
    acc[6] = fmaf(zq, wv1.z, acc[6]);
    acc[7] = fmaf(zq, wv1.w, acc[7]);
  }
  int n = n0+pos;
  int hh = n>>5, ww = n&31;
  float* outp = out + (b<<18) + ((2*hh + (r>>1))<<6) + 2*ww + (r&1);
  #pragma unroll
  for (int oo=0;oo<8;oo++)
    outp[(og*8+oo)<<12] = acc[oo];
}

extern "C" void kernel_launch(void* const* d_in, const int* in_sizes, int n_in,
                              void* d_out, int out_size){
  const float* x       = (const float*)d_in[0];
  const float* w_sq1   = (const float*)d_in[1];
  const float* b_sq1   = (const float*)d_in[2];
  const float* w_sq2   = (const float*)d_in[3];
  const float* b_sq2   = (const float*)d_in[4];
  const float* ca_wqkv = (const float*)d_in[5];
  const float* ca_bqkv = (const float*)d_in[6];
  const float* ca_t    = (const float*)d_in[7];
  const float* ca_wf   = (const float*)d_in[8];
  const float* ca_bf   = (const float*)d_in[9];
  const float* sa_wqkv = (const float*)d_in[10];
  const float* sa_bqkv = (const float*)d_in[11];
  const float* sa_t    = (const float*)d_in[12];
  const float* sa_wf   = (const float*)d_in[13];
  const float* sa_bf   = (const float*)d_in[14];
  const float* w_un1   = (const float*)d_in[15];
  const float* b_un1   = (const float*)d_in[16];
  const float* w_un2   = (const float*)d_in[17];
  const float* b_un2   = (const float*)d_in[18];
  float* out = (float*)d_out;

  k_squeeze<<<dim3(16,4,2),256>>>(x, w_sq1, b_sq1, w_sq2, b_sq2);
  k_chattn<<<dim3(32,2),256>>>(ca_wqkv, ca_bqkv, ca_t, ca_wf, ca_bf);
  k_spattn<<<dim3(64,2),256>>>(sa_wqkv, sa_bqkv, sa_t);
  k_fuse<<<dim3(128,2),256>>>(sa_wf, sa_bf, w_un1, b_un1, w_un2, b_un2, out);
}